// round 5
// baseline (speedup 1.0000x reference)
#include <cuda_runtime.h>
#include <math.h>

#define BB  32
#define NN  1024
#define FIN 6
#define F1  128
#define F2  512
#define F3  1024
#define CLS 40

// ---------------- scratch (static __device__ — no allocation allowed) ----------------
__device__ float g_L   [(size_t)BB * NN * NN];   // adjacency -> Laplacian, 128 MB
__device__ float g_feat[(size_t)BB * NN * F3];   // layer1 out (128) / layer3 out (1024)
__device__ float g_mid [(size_t)BB * NN * F2];   // layer2 out (512)
__device__ float g_t1  [(size_t)BB * NN * F2];   // x1 = L x0   (max Fin = 512)
__device__ float g_t2  [(size_t)BB * NN * F2];   // x2 = 2 L x1 - x0
__device__ float g_sq  [BB * NN];
__device__ float g_dis [BB * NN];
__device__ float g_pool[BB * F3];
__device__ float g_fc1 [BB * 512];
__device__ float g_fc2 [BB * 128];

// ---------------- row squared-norms: sq[b,n] = sum_f x^2 ----------------
__global__ void rowsq_kernel(const float* __restrict__ x, float* __restrict__ sq, int F) {
    int row  = blockIdx.x * (blockDim.x / 32) + (threadIdx.x >> 5);
    int lane = threadIdx.x & 31;
    if (row >= BB * NN) return;
    const float* p = x + (size_t)row * F;
    float s = 0.f;
    for (int f = lane; f < F; f += 32) { float v = p[f]; s += v * v; }
    #pragma unroll
    for (int o = 16; o; o >>= 1) s += __shfl_down_sync(0xffffffffu, s, o);
    if (lane == 0) sq[row] = s;
}

// ---------------- A[b,n,m] = exp(2*<x_n,x_m> - sq_n - sq_m) ----------------
__global__ void gram_exp_kernel(const float* __restrict__ X, const float* __restrict__ sq,
                                float* __restrict__ Aout, int F) {
    int b = blockIdx.z;
    const float* Xb  = X   + (size_t)b * NN * F;
    float*       Ab  = Aout + (size_t)b * NN * NN;
    const float* sqb = sq  + b * NN;

    int row0 = blockIdx.y * 64, col0 = blockIdx.x * 64;
    __shared__ float As[16][65];
    __shared__ float Bs[16][65];
    int tid = threadIdx.y * 16 + threadIdx.x;

    float acc[4][4];
    #pragma unroll
    for (int i = 0; i < 4; i++)
        #pragma unroll
        for (int j = 0; j < 4; j++) acc[i][j] = 0.f;

    for (int k0 = 0; k0 < F; k0 += 16) {
        #pragma unroll
        for (int t = 0; t < 4; t++) {
            int e = tid + t * 256;
            int r = e >> 4, k = e & 15;
            int kk = k0 + k;
            As[k][r] = (kk < F) ? Xb[(size_t)(row0 + r) * F + kk] : 0.f;
        }
        #pragma unroll
        for (int t = 0; t < 4; t++) {
            int e = tid + t * 256;
            int c = e >> 4, k = e & 15;
            int kk = k0 + k;
            Bs[k][c] = (kk < F) ? Xb[(size_t)(col0 + c) * F + kk] : 0.f;
        }
        __syncthreads();
        #pragma unroll
        for (int k = 0; k < 16; k++) {
            float a[4], bv[4];
            #pragma unroll
            for (int i = 0; i < 4; i++) a[i]  = As[k][threadIdx.y * 4 + i];
            #pragma unroll
            for (int j = 0; j < 4; j++) bv[j] = Bs[k][threadIdx.x * 4 + j];
            #pragma unroll
            for (int i = 0; i < 4; i++)
                #pragma unroll
                for (int j = 0; j < 4; j++) acc[i][j] += a[i] * bv[j];
        }
        __syncthreads();
    }

    #pragma unroll
    for (int i = 0; i < 4; i++) {
        int r = row0 + threadIdx.y * 4 + i;
        float sr = sqb[r];
        #pragma unroll
        for (int j = 0; j < 4; j++) {
            int c = col0 + threadIdx.x * 4 + j;
            Ab[(size_t)r * NN + c] = expf(2.f * acc[i][j] - sr - sqb[c]);
        }
    }
}

// ---------------- dis[b,n] = 1/sqrt(sum_m A[b,n,m]) ----------------
__global__ void deg_kernel(const float* __restrict__ A, float* __restrict__ dis) {
    int row  = blockIdx.x * (blockDim.x / 32) + (threadIdx.x >> 5);
    int lane = threadIdx.x & 31;
    if (row >= BB * NN) return;
    const float* p = A + (size_t)row * NN;
    float s = 0.f;
    for (int m = lane; m < NN; m += 32) s += p[m];
    #pragma unroll
    for (int o = 16; o; o >>= 1) s += __shfl_down_sync(0xffffffffu, s, o);
    if (lane == 0) dis[row] = 1.f / sqrtf(s);
}

// ---------------- L = I - dis_n * A * dis_m (in place) ----------------
__global__ void scaleL_kernel(float* __restrict__ L, const float* __restrict__ dis) {
    size_t total  = (size_t)BB * NN * NN;
    size_t stride = (size_t)gridDim.x * blockDim.x;
    for (size_t idx = (size_t)blockIdx.x * blockDim.x + threadIdx.x; idx < total; idx += stride) {
        size_t bn = idx >> 10;            // / NN
        int m = (int)(idx & (NN - 1));
        int b = (int)(bn >> 10);
        int n = (int)(bn & (NN - 1));
        float v = dis[b * NN + n] * L[idx] * dis[b * NN + m];
        L[idx] = (n == m ? 1.f : 0.f) - v;
    }
}

// ---------------- generic batched SGEMM: C = alpha*A@B + beta*Cin + bias (+relu) ----------------
__global__ void gemm_kernel(const float* __restrict__ A, const float* __restrict__ B,
                            const float* __restrict__ Cin, const float* __restrict__ bias,
                            float* __restrict__ C,
                            int M, int Nc, int K,
                            long long sA, long long sB, long long sCin, long long sC,
                            float alpha, float beta, int relu) {
    int bz = blockIdx.z;
    A += (size_t)bz * sA;
    B += (size_t)bz * sB;
    C += (size_t)bz * sC;
    if (Cin) Cin += (size_t)bz * sCin;

    int row0 = blockIdx.y * 64, col0 = blockIdx.x * 64;
    __shared__ float As[16][65];
    __shared__ float Bs[16][65];
    int tid = threadIdx.y * 16 + threadIdx.x;

    float acc[4][4];
    #pragma unroll
    for (int i = 0; i < 4; i++)
        #pragma unroll
        for (int j = 0; j < 4; j++) acc[i][j] = 0.f;

    for (int k0 = 0; k0 < K; k0 += 16) {
        #pragma unroll
        for (int t = 0; t < 4; t++) {
            int e = tid + t * 256;
            int r = e >> 4, k = e & 15;
            int kk = k0 + k, rr = row0 + r;
            As[k][r] = (kk < K && rr < M) ? A[(size_t)rr * K + kk] : 0.f;
        }
        #pragma unroll
        for (int t = 0; t < 4; t++) {
            int e = tid + t * 256;
            int k = e >> 6, c = e & 63;
            int kk = k0 + k, cc = col0 + c;
            Bs[k][c] = (kk < K && cc < Nc) ? B[(size_t)kk * Nc + cc] : 0.f;
        }
        __syncthreads();
        #pragma unroll
        for (int k = 0; k < 16; k++) {
            float a[4], bv[4];
            #pragma unroll
            for (int i = 0; i < 4; i++) a[i]  = As[k][threadIdx.y * 4 + i];
            #pragma unroll
            for (int j = 0; j < 4; j++) bv[j] = Bs[k][threadIdx.x * 4 + j];
            #pragma unroll
            for (int i = 0; i < 4; i++)
                #pragma unroll
                for (int j = 0; j < 4; j++) acc[i][j] += a[i] * bv[j];
        }
        __syncthreads();
    }

    #pragma unroll
    for (int i = 0; i < 4; i++) {
        int r = row0 + threadIdx.y * 4 + i;
        if (r >= M) continue;
        #pragma unroll
        for (int j = 0; j < 4; j++) {
            int c = col0 + threadIdx.x * 4 + j;
            if (c >= Nc) continue;
            float v = alpha * acc[i][j];
            if (Cin)  v += beta * Cin[(size_t)r * Nc + c];
            if (bias) v += bias[c];
            if (relu) v = fmaxf(v, 0.f);
            C[(size_t)r * Nc + c] = v;
        }
    }
}

// ---------------- global max pool over n ----------------
__global__ void maxpool_kernel(const float* __restrict__ X, float* __restrict__ out) {
    int f = blockIdx.x * blockDim.x + threadIdx.x;
    int b = blockIdx.y;
    if (f >= F3) return;
    const float* p = X + (size_t)b * NN * F3 + f;
    float m = -INFINITY;
    for (int n = 0; n < NN; n++) m = fmaxf(m, p[(size_t)n * F3]);
    out[b * F3 + f] = m;
}

// ---------------- host orchestration ----------------
static void run_gemm(const float* A, const float* B, const float* Cin, const float* bias,
                     float* C, int M, int Nc, int K,
                     long long sA, long long sB, long long sCin, long long sC,
                     float alpha, float beta, int relu, int batch) {
    dim3 grid((Nc + 63) / 64, (M + 63) / 64, batch);
    gemm_kernel<<<grid, dim3(16, 16)>>>(A, B, Cin, bias, C, M, Nc, K,
                                        sA, sB, sCin, sC, alpha, beta, relu);
}

static void run_layer(const float* xin, int Fin, int Fout,
                      const float* W, const float* bias, float* xout,
                      float* L, float* sq, float* dis, float* t1, float* t2) {
    rowsq_kernel<<<BB * NN / 8, 256>>>(xin, sq, Fin);
    gram_exp_kernel<<<dim3(NN / 64, NN / 64, BB), dim3(16, 16)>>>(xin, sq, L, Fin);
    deg_kernel<<<BB * NN / 8, 256>>>(L, dis);
    scaleL_kernel<<<8192, 256>>>(L, dis);

    long long sNF = (long long)NN * Fin;
    long long sLL = (long long)NN * NN;
    long long sNO = (long long)NN * Fout;

    // t1 = L @ xin
    run_gemm(L, xin, nullptr, nullptr, t1, NN, Fin, NN, sLL, sNF, 0, sNF, 1.f, 0.f, 0, BB);
    // t2 = 2 L @ t1 - xin
    run_gemm(L, t1, xin, nullptr, t2, NN, Fin, NN, sLL, sNF, sNF, sNF, 2.f, -1.f, 0, BB);
    // xout = xin @ W0
    run_gemm(xin, W, nullptr, nullptr, xout, NN, Fout, Fin, sNF, 0, 0, sNO, 1.f, 0.f, 0, BB);
    // xout += t1 @ W1
    run_gemm(t1, W + (size_t)Fin * Fout, xout, nullptr, xout, NN, Fout, Fin,
             sNF, 0, sNO, sNO, 1.f, 1.f, 0, BB);
    // xout = relu(xout + t2 @ W2 + bias)
    run_gemm(t2, W + 2 * (size_t)Fin * Fout, xout, bias, xout, NN, Fout, Fin,
             sNF, 0, sNO, sNO, 1.f, 1.f, 1, BB);
}

extern "C" void kernel_launch(void* const* d_in, const int* in_sizes, int n_in,
                              void* d_out, int out_size) {
    const float* x     = (const float*)d_in[0];
    const float* W1    = (const float*)d_in[1];
    const float* b1    = (const float*)d_in[2];
    const float* W2    = (const float*)d_in[3];
    const float* b2    = (const float*)d_in[4];
    const float* W3    = (const float*)d_in[5];
    const float* b3    = (const float*)d_in[6];
    const float* fc1_w = (const float*)d_in[7];
    const float* fc1_b = (const float*)d_in[8];
    const float* fc2_w = (const float*)d_in[9];
    const float* fc2_b = (const float*)d_in[10];
    const float* fc3_w = (const float*)d_in[11];
    const float* fc3_b = (const float*)d_in[12];

    float *L, *feat, *mid, *t1, *t2, *sq, *dis, *pool, *fc1b, *fc2b;
    cudaGetSymbolAddress((void**)&L,    g_L);
    cudaGetSymbolAddress((void**)&feat, g_feat);
    cudaGetSymbolAddress((void**)&mid,  g_mid);
    cudaGetSymbolAddress((void**)&t1,   g_t1);
    cudaGetSymbolAddress((void**)&t2,   g_t2);
    cudaGetSymbolAddress((void**)&sq,   g_sq);
    cudaGetSymbolAddress((void**)&dis,  g_dis);
    cudaGetSymbolAddress((void**)&pool, g_pool);
    cudaGetSymbolAddress((void**)&fc1b, g_fc1);
    cudaGetSymbolAddress((void**)&fc2b, g_fc2);

    // three Chebyshev graph-conv layers
    run_layer(x,    FIN, F1, W1, b1, feat, L, sq, dis, t1, t2);   // [B,N,128]
    run_layer(feat, F1,  F2, W2, b2, mid,  L, sq, dis, t1, t2);   // [B,N,512]
    run_layer(mid,  F2,  F3, W3, b3, feat, L, sq, dis, t1, t2);   // [B,N,1024]

    // global max pool
    maxpool_kernel<<<dim3((F3 + 255) / 256, BB), 256>>>(feat, pool);

    // FC head
    run_gemm(pool, fc1_w, nullptr, fc1_b, fc1b, BB, 512, 1024, 0, 0, 0, 0, 1.f, 0.f, 1, 1);
    run_gemm(fc1b, fc2_w, nullptr, fc2_b, fc2b, BB, 128, 512,  0, 0, 0, 0, 1.f, 0.f, 1, 1);
    run_gemm(fc2b, fc3_w, nullptr, fc3_b, (float*)d_out, BB, CLS, 128,
             0, 0, 0, 0, 1.f, 0.f, 0, 1);
}